// round 14
// baseline (speedup 1.0000x reference)
#include <cuda_runtime.h>
#include <cuda_bf16.h>
#include <cstdint>

#define DD 64
#define KC 512
#define ROWSB 128
#define NTHR 512
#define NCTA 148
#define MARG_P 22000u       // 2e-5 dist margin * 2^21 * 512
#define SCALE 2097152.0f    // 2^21
#define NEG2SCALE -4194304.0f

#if defined(__CUDA_ARCH__) && (defined(__CUDA_ARCH_FEAT_SM103_ALL) || defined(__CUDA_ARCH_FEAT_SM100_ALL) || defined(__CUDA_ARCH_FEAT_SM101_ALL))
#define HAS_TCGEN05 1
#else
#define HAS_TCGEN05 0
#endif

// ---- smem byte offsets ----
#define MB_QD(q)   ((q) * 8)           // 4 barriers: quarter q MMAs done (count 1)
#define TMEM_SLOT  32
#define CS_OFF     128                 // 512 f32 exact csq
#define PRE_OFF    2176                // 512 f32 (csq+2)*2^21
#define XS_OFF     4224                // 2 x 128 f32
#define QT_OFF     5248                // 512 threads x uint2 (top-2 keys)
#define BD_OFF     9344                // 4 x 128 f32 exact best per (quarter,row)
#define BI_OFF     11392               // 4 x 128 i32
#define SIDX_OFF   13440               // 128 i32
#define A_OFF(b,s) (14336 + ((b) * 2 + (s)) * 16384)   // 2 bufs x {h,l}
#define B_OFF(s)   (79872 + (s) * 65536)               // {h,l} 64KB each, SW128
#define SMEM_TOTAL 210944

__device__ __forceinline__ uint32_t smem_u32(const void* p) {
    uint32_t a;
    asm("{ .reg .u64 t; cvta.to.shared.u64 t, %1; cvt.u32.u64 %0, t; }" : "=r"(a) : "l"(p));
    return a;
}
__device__ __forceinline__ uint32_t sw128(uint32_t off) { return off ^ ((off >> 3) & 0x70); }

#if HAS_TCGEN05
__device__ __forceinline__ uint32_t elect1() {
    uint32_t p;
    asm volatile("{ .reg .pred p; elect.sync _|p, 0xFFFFFFFF; selp.b32 %0, 1, 0, p; }" : "=r"(p));
    return p;
}
__device__ __forceinline__ void mbar_init(uint32_t a, uint32_t cnt) {
    asm volatile("mbarrier.init.shared.b64 [%0], %1;" :: "r"(a), "r"(cnt) : "memory");
}
__device__ __forceinline__ void mbar_wait(uint32_t a, uint32_t parity) {
    asm volatile(
        "{\n\t.reg .pred P;\n"
        "WL_%=:\n\t"
        "mbarrier.try_wait.parity.acquire.cta.shared::cta.b64 P, [%0], %1, 0x989680;\n\t"
        "@!P bra WL_%=;\n\t}"
        :: "r"(a), "r"(parity) : "memory");
}
__device__ __forceinline__ void fence_async() {
    asm volatile("fence.proxy.async.shared::cta;" ::: "memory");
}
__device__ __forceinline__ void tmem_alloc(uint32_t slot, uint32_t ncols) {
    asm volatile("tcgen05.alloc.cta_group::1.sync.aligned.shared::cta.b32 [%0], %1;"
                 :: "r"(slot), "r"(ncols) : "memory");
}
__device__ __forceinline__ void tmem_dealloc(uint32_t base, uint32_t ncols) {
    asm volatile("tcgen05.dealloc.cta_group::1.sync.aligned.b32 %0, %1;" :: "r"(base), "r"(ncols));
}
__device__ __forceinline__ void mma_f16_ss(uint32_t d, uint64_t ad, uint64_t bd,
                                           uint32_t idesc, uint32_t en) {
    asm volatile(
        "{\n\t.reg .pred p;\n\t"
        "setp.ne.u32 p, %5, 0;\n\t"
        "tcgen05.mma.cta_group::1.kind::f16 [%0], %1, %2, %3, {%4, %4, %4, %4}, p;\n\t}"
        :: "r"(d), "l"(ad), "l"(bd), "r"(idesc), "r"(0u), "r"(en) : "memory");
}
__device__ __forceinline__ void mma_commit(uint32_t mbar) {
    asm volatile("tcgen05.commit.cta_group::1.mbarrier::arrive::one.shared::cluster.b64 [%0];"
                 :: "r"(mbar) : "memory");
}
__device__ __forceinline__ void fence_tc_after() {
    asm volatile("tcgen05.fence::after_thread_sync;" ::: "memory");
}
__device__ __forceinline__ void fence_tc_before() {
    asm volatile("tcgen05.fence::before_thread_sync;" ::: "memory");
}
#define LDTM_X32(r, a) \
    asm volatile("tcgen05.ld.sync.aligned.32x32b.x32.b32 " \
        "{%0,%1,%2,%3,%4,%5,%6,%7,%8,%9,%10,%11,%12,%13,%14,%15," \
        "%16,%17,%18,%19,%20,%21,%22,%23,%24,%25,%26,%27,%28,%29,%30,%31}, [%32];" \
        : "=r"((r)[0]),"=r"((r)[1]),"=r"((r)[2]),"=r"((r)[3]),"=r"((r)[4]),"=r"((r)[5]), \
          "=r"((r)[6]),"=r"((r)[7]),"=r"((r)[8]),"=r"((r)[9]),"=r"((r)[10]),"=r"((r)[11]), \
          "=r"((r)[12]),"=r"((r)[13]),"=r"((r)[14]),"=r"((r)[15]),"=r"((r)[16]),"=r"((r)[17]), \
          "=r"((r)[18]),"=r"((r)[19]),"=r"((r)[20]),"=r"((r)[21]),"=r"((r)[22]),"=r"((r)[23]), \
          "=r"((r)[24]),"=r"((r)[25]),"=r"((r)[26]),"=r"((r)[27]),"=r"((r)[28]),"=r"((r)[29]), \
          "=r"((r)[30]),"=r"((r)[31]) : "r"(a))
__device__ __forceinline__ void tmem_wait_ld() {
    asm volatile("tcgen05.wait::ld.sync.aligned;" ::: "memory");
}
#endif

#define DESC_BASE 0x4000404000010000ULL
__device__ __forceinline__ uint64_t mk_desc(uint32_t addr) {
    return DESC_BASE | ((uint64_t)(addr >> 4) & 0x3FFF);
}
#define IDESC 0x8200490u   // f32 acc, bf16 a/b, M=128, N=128 (proven R3-R13)

__device__ __forceinline__ uint32_t packbf(float a, float b) {
    return (uint32_t)__bfloat16_as_ushort(__float2bfloat16(a)) |
           ((uint32_t)__bfloat16_as_ushort(__float2bfloat16(b)) << 16);
}
__device__ __forceinline__ uint32_t umn(uint32_t a, uint32_t b) { return a < b ? a : b; }
__device__ __forceinline__ uint32_t umx(uint32_t a, uint32_t b) { return a > b ? a : b; }

__global__ void __launch_bounds__(NTHR, 1)
vq_persist(const float* __restrict__ x, const float* __restrict__ cbk,
           float* __restrict__ out, int n) {
    extern __shared__ char smem[];
    const int tid = threadIdx.x;
    const int bid = blockIdx.x;
    const size_t nD = (size_t)n * DD;
    float* Cs = (float*)(smem + CS_OFF);

#if HAS_TCGEN05
    const uint32_t sb = smem_u32(smem);
    const int wid = tid >> 5;
    const int lane = tid & 31;
    float* pre = (float*)(smem + PRE_OFF);
    float* XsS = (float*)(smem + XS_OFF);
    uint32_t* QT = (uint32_t*)(smem + QT_OFF);
    float* BD = (float*)(smem + BD_OFF);
    int* BI = (int*)(smem + BI_OFF);
    int* sidx = (int*)(smem + SIDX_OFF);

    const int ntiles = (n + ROWSB - 1) / ROWSB;
    const int nt = (ntiles > bid) ? (ntiles - bid + NCTA - 1) / NCTA : 0;

    // ---------- startup ----------
    if (tid == 0) {
        for (int q = 0; q < 4; ++q) mbar_init(sb + MB_QD(q), 1);
    }
    if (wid == 0) tmem_alloc(sb + TMEM_SLOT, 512);

    // B limbs: 512x64 -> bf16 h,l SW128 (128B per code row each)
    for (int i = tid; i < KC * DD / 4; i += NTHR) {
        int code = i >> 4, kq = i & 15;
        float4 v = __ldg(((const float4*)cbk) + i);
        __nv_bfloat16 hx = __float2bfloat16(v.x), hy = __float2bfloat16(v.y);
        __nv_bfloat16 hz = __float2bfloat16(v.z), hw = __float2bfloat16(v.w);
        uint64_t uh = (uint64_t)((uint32_t)__bfloat16_as_ushort(hx) |
                                 ((uint32_t)__bfloat16_as_ushort(hy) << 16)) |
                      ((uint64_t)((uint32_t)__bfloat16_as_ushort(hz) |
                                 ((uint32_t)__bfloat16_as_ushort(hw) << 16)) << 32);
        uint64_t ul = (uint64_t)packbf(v.x - __bfloat162float(hx), v.y - __bfloat162float(hy)) |
                      ((uint64_t)packbf(v.z - __bfloat162float(hz), v.w - __bfloat162float(hw)) << 32);
        uint32_t so = sw128(code * 128 + kq * 8);
        *(uint64_t*)(smem + B_OFF(0) + so) = uh;
        *(uint64_t*)(smem + B_OFF(1) + so) = ul;
    }
    // exact csq (reference rounding) + filter prescale
    for (int c = tid; c < KC; c += NTHR) {
        float s = 0.0f;
        const float* cr = cbk + c * DD;
        for (int k = 0; k < DD; ++k) {
            float v = __ldg(cr + k);
            s = __fadd_rn(s, __fmul_rn(v, v));
        }
        Cs[c] = s;
        pre[c] = (s + 2.0f) * SCALE;
    }
    // build A[0] (h,l) + xs for tile 0
    if (tid < 128 && nt > 0) {
        const int grow = bid * ROWSB + tid;
        float s = 0.0f;
        #pragma unroll
        for (int k4 = 0; k4 < 16; ++k4) {
            float4 v = make_float4(0.f, 0.f, 0.f, 0.f);
            if (grow < n) v = __ldg(((const float4*)(x + (size_t)grow * DD)) + k4);
            s = __fadd_rn(s, __fmul_rn(v.x, v.x));
            s = __fadd_rn(s, __fmul_rn(v.y, v.y));
            s = __fadd_rn(s, __fmul_rn(v.z, v.z));
            s = __fadd_rn(s, __fmul_rn(v.w, v.w));
            __nv_bfloat16 hx = __float2bfloat16(v.x), hy = __float2bfloat16(v.y);
            __nv_bfloat16 hz = __float2bfloat16(v.z), hw = __float2bfloat16(v.w);
            uint64_t uh = (uint64_t)((uint32_t)__bfloat16_as_ushort(hx) |
                                     ((uint32_t)__bfloat16_as_ushort(hy) << 16)) |
                          ((uint64_t)((uint32_t)__bfloat16_as_ushort(hz) |
                                     ((uint32_t)__bfloat16_as_ushort(hw) << 16)) << 32);
            uint64_t ul = (uint64_t)packbf(v.x - __bfloat162float(hx), v.y - __bfloat162float(hy)) |
                          ((uint64_t)packbf(v.z - __bfloat162float(hz), v.w - __bfloat162float(hw)) << 32);
            uint32_t so = sw128(tid * 128 + k4 * 8);
            *(uint64_t*)(smem + A_OFF(0, 0) + so) = uh;
            *(uint64_t*)(smem + A_OFF(0, 1) + so) = ul;
        }
        XsS[tid] = s;
    }
    fence_async();
    __syncthreads();
    const uint32_t tmem = *(volatile uint32_t*)(smem + TMEM_SLOT);

    const int sub = wid & 3;
    const int qh = wid >> 2;              // code quarter: cols [qh*128, qh*128+128)
    const int srow = sub * 32 + lane;
    const int cbase = qh * 128;
    const uint64_t bdh = mk_desc(sb + B_OFF(0));
    const uint64_t bdl = mk_desc(sb + B_OFF(1));

    const int rrow = tid & 127;           // refine row
    const int rq = tid >> 7;              // refine quarter

    // ---------- main loop ----------
    for (int it = 0; it < nt; ++it) {
        const int buf = it & 1;
        const int tile = bid + it * NCTA;

        // 1) issue 48 MMAs with a commit after each quarter's 12
        if (wid == 0) {
            if (elect1()) {
                const uint64_t adh = mk_desc(sb + A_OFF(buf, 0));
                const uint64_t adl = mk_desc(sb + A_OFF(buf, 1));
                for (int q = 0; q < 4; ++q) {
                    const uint32_t dcol = tmem + q * 128;
                    const uint32_t qo = (uint32_t)(q * 1024);
                    #pragma unroll
                    for (int k = 0; k < 4; ++k)
                        mma_f16_ss(dcol, adh + k * 2, bdh + qo + k * 2, IDESC, k != 0);
                    #pragma unroll
                    for (int k = 0; k < 4; ++k)
                        mma_f16_ss(dcol, adh + k * 2, bdl + qo + k * 2, IDESC, 1);
                    #pragma unroll
                    for (int k = 0; k < 4; ++k)
                        mma_f16_ss(dcol, adl + k * 2, bdh + qo + k * 2, IDESC, 1);
                    mma_commit(sb + MB_QD(q));
                }
            }
        }

        // 2) build A for tile it+1 (overlaps MMA)
        if (tid < 128 && it + 1 < nt) {
            const int ab = (it + 1) & 1;
            const int grow2 = (bid + (it + 1) * NCTA) * ROWSB + tid;
            float s = 0.0f;
            #pragma unroll
            for (int k4 = 0; k4 < 16; ++k4) {
                float4 v = make_float4(0.f, 0.f, 0.f, 0.f);
                if (grow2 < n) v = __ldg(((const float4*)(x + (size_t)grow2 * DD)) + k4);
                s = __fadd_rn(s, __fmul_rn(v.x, v.x));
                s = __fadd_rn(s, __fmul_rn(v.y, v.y));
                s = __fadd_rn(s, __fmul_rn(v.z, v.z));
                s = __fadd_rn(s, __fmul_rn(v.w, v.w));
                __nv_bfloat16 hx = __float2bfloat16(v.x), hy = __float2bfloat16(v.y);
                __nv_bfloat16 hz = __float2bfloat16(v.z), hw = __float2bfloat16(v.w);
                uint64_t uh = (uint64_t)((uint32_t)__bfloat16_as_ushort(hx) |
                                         ((uint32_t)__bfloat16_as_ushort(hy) << 16)) |
                              ((uint64_t)((uint32_t)__bfloat16_as_ushort(hz) |
                                         ((uint32_t)__bfloat16_as_ushort(hw) << 16)) << 32);
                uint64_t ul = (uint64_t)packbf(v.x - __bfloat162float(hx), v.y - __bfloat162float(hy)) |
                              ((uint64_t)packbf(v.z - __bfloat162float(hz), v.w - __bfloat162float(hw)) << 32);
                uint32_t so = sw128(tid * 128 + k4 * 8);
                *(uint64_t*)(smem + A_OFF(ab, 0) + so) = uh;
                *(uint64_t*)(smem + A_OFF(ab, 1) + so) = ul;
            }
            XsS[ab * 128 + tid] = s;
            fence_async();
        }

        // 3) wait this quarter's MMAs only (quarter 0 ready earliest)
        mbar_wait(sb + MB_QD(qh), (uint32_t)(it & 1));
        fence_tc_after();

        // 4) branchless top-2 packed-key filter, software-pipelined LDTM
        uint32_t m1 = 0xFFFFFFFFu, m2 = 0xFFFFFFFFu;
        {
            uint32_t rgA[32], rgB[32];
            LDTM_X32(rgA, tmem + cbase);
            tmem_wait_ld();
            #pragma unroll
            for (int b = 0; b < 4; ++b) {
                const uint32_t* cur = (b & 1) ? rgB : rgA;
                uint32_t* nxt = (b & 1) ? rgA : rgB;
                if (b < 3) LDTM_X32(nxt, tmem + cbase + (b + 1) * 32);
                const int base = cbase + b * 32;
                #pragma unroll
                for (int j4 = 0; j4 < 8; ++j4) {
                    float4 p4 = *(const float4*)(pre + base + j4 * 4);
                    #pragma unroll
                    for (int jj = 0; jj < 4; ++jj) {
                        float pv = (jj == 0) ? p4.x : (jj == 1) ? p4.y : (jj == 2) ? p4.z : p4.w;
                        float kf = __fmaf_rn(__uint_as_float(cur[j4 * 4 + jj]), NEG2SCALE, pv);
                        uint32_t pk = __float2uint_rz(kf) * 512u + (uint32_t)(base + j4 * 4 + jj);
                        uint32_t t1 = umx(m1, pk);
                        m1 = umn(m1, pk);
                        m2 = umn(m2, t1);
                    }
                }
                if (b < 3) tmem_wait_ld();
            }
        }
        fence_tc_before();
        {
            uint2 u; u.x = m1; u.y = m2;
            *(uint2*)(QT + ((qh * 128 + srow) << 1)) = u;
        }
        __syncthreads();

        // 5) refine distributed over 512 threads: (row, quarter) each
        {
            const int grow = tile * ROWSB + rrow;
            float best = 3.4e38f; int bib = 0x7FFFFFFF;
            if (grow < n) {
                uint2 u0 = *(const uint2*)(QT + ((0 * 128 + rrow) << 1));
                uint2 u1 = *(const uint2*)(QT + ((1 * 128 + rrow) << 1));
                uint2 u2 = *(const uint2*)(QT + ((2 * 128 + rrow) << 1));
                uint2 u3 = *(const uint2*)(QT + ((3 * 128 + rrow) << 1));
                uint32_t gmin = umn(umn(u0.x, u1.x), umn(u2.x, u3.x));
                const uint32_t lim = gmin + MARG_P;
                uint2 mine = (rq == 0) ? u0 : (rq == 1) ? u1 : (rq == 2) ? u2 : u3;
                if (mine.x <= lim) {  // this quarter has at least one candidate
                    const float xs = XsS[buf * 128 + rrow];
                    const float4* xr = (const float4*)(x + (size_t)grow * DD);
                    if (mine.y <= lim) {
                        // rare: 3rd candidate could hide behind top-2 -> exact rescan of quarter
                        const int cb = rq * 128;
                        for (int code = cb; code < cb + 128; ++code) {
                            const float4* cr = (const float4*)(cbk + code * DD);
                            float dot = 0.0f;
                            #pragma unroll
                            for (int k4 = 0; k4 < 16; ++k4) {
                                float4 a = __ldg(xr + k4);
                                float4 bb = __ldg(cr + k4);
                                dot = __fmaf_rn(a.x, bb.x, dot);
                                dot = __fmaf_rn(a.y, bb.y, dot);
                                dot = __fmaf_rn(a.z, bb.z, dot);
                                dot = __fmaf_rn(a.w, bb.w, dot);
                            }
                            float d = __fmaf_rn(-2.0f, dot, __fadd_rn(xs, Cs[code]));
                            if (d < best) { best = d; bib = code; }  // ascending: lowest-index ties
                        }
                    } else {
                        const int code = (int)(mine.x & 511u);
                        const float4* cr = (const float4*)(cbk + code * DD);
                        float dot = 0.0f;
                        #pragma unroll
                        for (int k4 = 0; k4 < 16; ++k4) {
                            float4 a = __ldg(xr + k4);
                            float4 bb = __ldg(cr + k4);
                            dot = __fmaf_rn(a.x, bb.x, dot);
                            dot = __fmaf_rn(a.y, bb.y, dot);
                            dot = __fmaf_rn(a.z, bb.z, dot);
                            dot = __fmaf_rn(a.w, bb.w, dot);
                        }
                        best = __fmaf_rn(-2.0f, dot, __fadd_rn(xs, Cs[code]));
                        bib = code;
                    }
                }
            }
            BD[rq * 128 + rrow] = best;
            BI[rq * 128 + rrow] = bib;
        }
        __syncthreads();

        // 6) merge 4 quarters (exact dist; equal -> lower code) -> index output
        if (tid < 128) {
            float bd = BD[tid]; int bi = BI[tid];
            #pragma unroll
            for (int g = 1; g < 4; ++g) {
                float d = BD[g * 128 + tid]; int ii = BI[g * 128 + tid];
                if (d < bd || (d == bd && ii < bi)) { bd = d; bi = ii; }
            }
            sidx[tid] = bi;
            const int g = tile * ROWSB + tid;
            if (g < n) out[2 * nD + g] = (float)bi;
        }
        __syncthreads();

        // 7) gather z_q_x / z_q_x_bar
        for (int i = tid; i < ROWSB * 32; i += NTHR) {
            const int row = i >> 5;
            const int d = (i >> 4) & 1;
            const int q = i & 15;
            const int g = tile * ROWSB + row;
            if (g < n) {
                float4 v = __ldg(((const float4*)cbk) + sidx[row] * 16 + q);
                ((float4*)(out + (size_t)d * nD + (size_t)g * DD))[q] = v;
            }
        }
    }

    __syncthreads();
    if (wid == 0) tmem_dealloc(tmem, 512);

#else
    // ============ generic-arch fallback (compile-only on GB300) ============
    for (int c = tid; c < KC; c += NTHR) {
        float s = 0.0f;
        const float* cr = cbk + c * DD;
        for (int k = 0; k < DD; ++k) {
            float v = cr[k];
            s = __fadd_rn(s, __fmul_rn(v, v));
        }
        Cs[c] = s;
    }
    __syncthreads();
    for (long long row = (long long)bid * NTHR + tid; row < n; row += (long long)gridDim.x * NTHR) {
        const float* xr = x + row * DD;
        float xv[DD];
        for (int k = 0; k < DD; ++k) xv[k] = xr[k];
        float xs = 0.0f;
        for (int k = 0; k < DD; ++k) xs = __fadd_rn(xs, __fmul_rn(xv[k], xv[k]));
        float best = 3.4e38f; int bi = 0;
        for (int c = 0; c < KC; ++c) {
            const float* cr = cbk + c * DD;
            float dot = 0.0f;
            for (int k = 0; k < DD; ++k) dot = __fmaf_rn(xv[k], cr[k], dot);
            float d = __fmaf_rn(-2.0f, dot, __fadd_rn(xs, Cs[c]));
            if (d < best) { best = d; bi = c; }
        }
        out[2 * nD + row] = (float)bi;
        const float* cr = cbk + bi * DD;
        for (int k = 0; k < DD; ++k) {
            out[(size_t)row * DD + k] = cr[k];
            out[nD + (size_t)row * DD + k] = cr[k];
        }
    }
#endif
}

extern "C" void kernel_launch(void* const* d_in, const int* in_sizes, int n_in,
                              void* d_out, int out_size) {
    const float* x = (const float*)d_in[0];
    const float* cbk = (const float*)d_in[1];
    float* out = (float*)d_out;
    const int n = in_sizes[0] / DD;

    cudaFuncSetAttribute(vq_persist, cudaFuncAttributeMaxDynamicSharedMemorySize, SMEM_TOTAL);
    vq_persist<<<NCTA, NTHR, SMEM_TOTAL>>>(x, cbk, out, n);
}

// round 15
// speedup vs baseline: 3.0271x; 3.0271x over previous
#include <cuda_runtime.h>
#include <cuda_bf16.h>
#include <cstdint>

#define DD 64
#define KC 512
#define ROWSB 128
#define NTHR 512
#define NCTA 148
#define MARG_P 22000u       // 2e-5 dist margin * 2^21 * 512
#define SCALE 2097152.0f    // 2^21
#define NEG2SCALE -4194304.0f

#if defined(__CUDA_ARCH__) && (defined(__CUDA_ARCH_FEAT_SM103_ALL) || defined(__CUDA_ARCH_FEAT_SM100_ALL) || defined(__CUDA_ARCH_FEAT_SM101_ALL))
#define HAS_TCGEN05 1
#else
#define HAS_TCGEN05 0
#endif

// ---- smem byte offsets ----
#define MB_QD(q)   ((q) * 8)           // 4 barriers: quarter q MMAs done (count 1)
#define TMEM_SLOT  32
#define CS_OFF     128                 // 512 f32 exact csq
#define PRE_OFF    2176                // 512 f32 (csq+2)*2^21
#define XS_OFF     4224                // 2 x 128 f32
#define QT_OFF     5248                // 512 threads x uint4 (top-3 keys)
#define BD_OFF     13440               // 4 x 128 f32 exact best per (quarter,row)
#define BI_OFF     15488               // 4 x 128 i32
#define SIDX_OFF   17536               // 128 i32
#define A_OFF(b,s) (18432 + ((b) * 2 + (s)) * 16384)   // 2 bufs x {h,l}
#define B_OFF(s)   (83968 + (s) * 65536)               // {h,l} 64KB each, SW128
#define SMEM_TOTAL 215040

__device__ __forceinline__ uint32_t smem_u32(const void* p) {
    uint32_t a;
    asm("{ .reg .u64 t; cvta.to.shared.u64 t, %1; cvt.u32.u64 %0, t; }" : "=r"(a) : "l"(p));
    return a;
}
__device__ __forceinline__ uint32_t sw128(uint32_t off) { return off ^ ((off >> 3) & 0x70); }

#if HAS_TCGEN05
__device__ __forceinline__ uint32_t elect1() {
    uint32_t p;
    asm volatile("{ .reg .pred p; elect.sync _|p, 0xFFFFFFFF; selp.b32 %0, 1, 0, p; }" : "=r"(p));
    return p;
}
__device__ __forceinline__ void mbar_init(uint32_t a, uint32_t cnt) {
    asm volatile("mbarrier.init.shared.b64 [%0], %1;" :: "r"(a), "r"(cnt) : "memory");
}
__device__ __forceinline__ void mbar_wait(uint32_t a, uint32_t parity) {
    asm volatile(
        "{\n\t.reg .pred P;\n"
        "WL_%=:\n\t"
        "mbarrier.try_wait.parity.acquire.cta.shared::cta.b64 P, [%0], %1, 0x989680;\n\t"
        "@!P bra WL_%=;\n\t}"
        :: "r"(a), "r"(parity) : "memory");
}
__device__ __forceinline__ void fence_async() {
    asm volatile("fence.proxy.async.shared::cta;" ::: "memory");
}
__device__ __forceinline__ void tmem_alloc(uint32_t slot, uint32_t ncols) {
    asm volatile("tcgen05.alloc.cta_group::1.sync.aligned.shared::cta.b32 [%0], %1;"
                 :: "r"(slot), "r"(ncols) : "memory");
}
__device__ __forceinline__ void tmem_dealloc(uint32_t base, uint32_t ncols) {
    asm volatile("tcgen05.dealloc.cta_group::1.sync.aligned.b32 %0, %1;" :: "r"(base), "r"(ncols));
}
__device__ __forceinline__ void mma_f16_ss(uint32_t d, uint64_t ad, uint64_t bd,
                                           uint32_t idesc, uint32_t en) {
    asm volatile(
        "{\n\t.reg .pred p;\n\t"
        "setp.ne.u32 p, %5, 0;\n\t"
        "tcgen05.mma.cta_group::1.kind::f16 [%0], %1, %2, %3, {%4, %4, %4, %4}, p;\n\t}"
        :: "r"(d), "l"(ad), "l"(bd), "r"(idesc), "r"(0u), "r"(en) : "memory");
}
__device__ __forceinline__ void mma_commit(uint32_t mbar) {
    asm volatile("tcgen05.commit.cta_group::1.mbarrier::arrive::one.shared::cluster.b64 [%0];"
                 :: "r"(mbar) : "memory");
}
__device__ __forceinline__ void fence_tc_after() {
    asm volatile("tcgen05.fence::after_thread_sync;" ::: "memory");
}
__device__ __forceinline__ void fence_tc_before() {
    asm volatile("tcgen05.fence::before_thread_sync;" ::: "memory");
}
#define LDTM_X32(r, a) \
    asm volatile("tcgen05.ld.sync.aligned.32x32b.x32.b32 " \
        "{%0,%1,%2,%3,%4,%5,%6,%7,%8,%9,%10,%11,%12,%13,%14,%15," \
        "%16,%17,%18,%19,%20,%21,%22,%23,%24,%25,%26,%27,%28,%29,%30,%31}, [%32];" \
        : "=r"((r)[0]),"=r"((r)[1]),"=r"((r)[2]),"=r"((r)[3]),"=r"((r)[4]),"=r"((r)[5]), \
          "=r"((r)[6]),"=r"((r)[7]),"=r"((r)[8]),"=r"((r)[9]),"=r"((r)[10]),"=r"((r)[11]), \
          "=r"((r)[12]),"=r"((r)[13]),"=r"((r)[14]),"=r"((r)[15]),"=r"((r)[16]),"=r"((r)[17]), \
          "=r"((r)[18]),"=r"((r)[19]),"=r"((r)[20]),"=r"((r)[21]),"=r"((r)[22]),"=r"((r)[23]), \
          "=r"((r)[24]),"=r"((r)[25]),"=r"((r)[26]),"=r"((r)[27]),"=r"((r)[28]),"=r"((r)[29]), \
          "=r"((r)[30]),"=r"((r)[31]) : "r"(a))
__device__ __forceinline__ void tmem_wait_ld() {
    asm volatile("tcgen05.wait::ld.sync.aligned;" ::: "memory");
}
#endif

#define DESC_BASE 0x4000404000010000ULL
__device__ __forceinline__ uint64_t mk_desc(uint32_t addr) {
    return DESC_BASE | ((uint64_t)(addr >> 4) & 0x3FFF);
}
#define IDESC 0x8200490u   // f32 acc, bf16 a/b, M=128, N=128 (proven R3-R14)

__device__ __forceinline__ uint32_t packbf(float a, float b) {
    return (uint32_t)__bfloat16_as_ushort(__float2bfloat16(a)) |
           ((uint32_t)__bfloat16_as_ushort(__float2bfloat16(b)) << 16);
}
__device__ __forceinline__ uint32_t umn(uint32_t a, uint32_t b) { return a < b ? a : b; }
__device__ __forceinline__ uint32_t umx(uint32_t a, uint32_t b) { return a > b ? a : b; }

__global__ void __launch_bounds__(NTHR, 1)
vq_persist(const float* __restrict__ x, const float* __restrict__ cbk,
           float* __restrict__ out, int n) {
    extern __shared__ char smem[];
    const int tid = threadIdx.x;
    const int bid = blockIdx.x;
    const size_t nD = (size_t)n * DD;
    float* Cs = (float*)(smem + CS_OFF);

#if HAS_TCGEN05
    const uint32_t sb = smem_u32(smem);
    const int wid = tid >> 5;
    const int lane = tid & 31;
    float* pre = (float*)(smem + PRE_OFF);
    float* XsS = (float*)(smem + XS_OFF);
    uint32_t* QT = (uint32_t*)(smem + QT_OFF);
    float* BD = (float*)(smem + BD_OFF);
    int* BI = (int*)(smem + BI_OFF);
    int* sidx = (int*)(smem + SIDX_OFF);

    const int ntiles = (n + ROWSB - 1) / ROWSB;
    const int nt = (ntiles > bid) ? (ntiles - bid + NCTA - 1) / NCTA : 0;

    // ---------- startup ----------
    if (tid == 0) {
        for (int q = 0; q < 4; ++q) mbar_init(sb + MB_QD(q), 1);
    }
    if (wid == 0) tmem_alloc(sb + TMEM_SLOT, 512);

    // B limbs: 512x64 -> bf16 h,l SW128 (128B per code row each)
    for (int i = tid; i < KC * DD / 4; i += NTHR) {
        int code = i >> 4, kq = i & 15;
        float4 v = __ldg(((const float4*)cbk) + i);
        __nv_bfloat16 hx = __float2bfloat16(v.x), hy = __float2bfloat16(v.y);
        __nv_bfloat16 hz = __float2bfloat16(v.z), hw = __float2bfloat16(v.w);
        uint64_t uh = (uint64_t)((uint32_t)__bfloat16_as_ushort(hx) |
                                 ((uint32_t)__bfloat16_as_ushort(hy) << 16)) |
                      ((uint64_t)((uint32_t)__bfloat16_as_ushort(hz) |
                                 ((uint32_t)__bfloat16_as_ushort(hw) << 16)) << 32);
        uint64_t ul = (uint64_t)packbf(v.x - __bfloat162float(hx), v.y - __bfloat162float(hy)) |
                      ((uint64_t)packbf(v.z - __bfloat162float(hz), v.w - __bfloat162float(hw)) << 32);
        uint32_t so = sw128(code * 128 + kq * 8);
        *(uint64_t*)(smem + B_OFF(0) + so) = uh;
        *(uint64_t*)(smem + B_OFF(1) + so) = ul;
    }
    // exact csq (reference rounding) + filter prescale
    for (int c = tid; c < KC; c += NTHR) {
        float s = 0.0f;
        const float* cr = cbk + c * DD;
        for (int k = 0; k < DD; ++k) {
            float v = __ldg(cr + k);
            s = __fadd_rn(s, __fmul_rn(v, v));
        }
        Cs[c] = s;
        pre[c] = (s + 2.0f) * SCALE;
    }

    // A builder (h,l limbs + exact xs) for tile index 'at' into buffer at&1
    auto build_A = [&](int at) {
        const int ab = at & 1;
        const int grow = (bid + at * NCTA) * ROWSB + tid;
        float s = 0.0f;
        #pragma unroll
        for (int k4 = 0; k4 < 16; ++k4) {
            float4 v = make_float4(0.f, 0.f, 0.f, 0.f);
            if (grow < n) v = __ldg(((const float4*)(x + (size_t)grow * DD)) + k4);
            s = __fadd_rn(s, __fmul_rn(v.x, v.x));
            s = __fadd_rn(s, __fmul_rn(v.y, v.y));
            s = __fadd_rn(s, __fmul_rn(v.z, v.z));
            s = __fadd_rn(s, __fmul_rn(v.w, v.w));
            __nv_bfloat16 hx = __float2bfloat16(v.x), hy = __float2bfloat16(v.y);
            __nv_bfloat16 hz = __float2bfloat16(v.z), hw = __float2bfloat16(v.w);
            uint64_t uh = (uint64_t)((uint32_t)__bfloat16_as_ushort(hx) |
                                     ((uint32_t)__bfloat16_as_ushort(hy) << 16)) |
                          ((uint64_t)((uint32_t)__bfloat16_as_ushort(hz) |
                                     ((uint32_t)__bfloat16_as_ushort(hw) << 16)) << 32);
            uint64_t ul = (uint64_t)packbf(v.x - __bfloat162float(hx), v.y - __bfloat162float(hy)) |
                          ((uint64_t)packbf(v.z - __bfloat162float(hz), v.w - __bfloat162float(hw)) << 32);
            uint32_t so = sw128(tid * 128 + k4 * 8);
            *(uint64_t*)(smem + A_OFF(ab, 0) + so) = uh;
            *(uint64_t*)(smem + A_OFF(ab, 1) + so) = ul;
        }
        XsS[ab * 128 + tid] = s;
        fence_async();
    };

    if (tid < 128 && nt > 0) build_A(0);
    fence_async();
    __syncthreads();
    const uint32_t tmem = *(volatile uint32_t*)(smem + TMEM_SLOT);

    const uint64_t bdh = mk_desc(sb + B_OFF(0));
    const uint64_t bdl = mk_desc(sb + B_OFF(1));

    // 48 MMAs for tile 'at', per-quarter commits (proven R13)
    auto issue_mma = [&](int at) {
        const uint64_t adh = mk_desc(sb + A_OFF(at & 1, 0));
        const uint64_t adl = mk_desc(sb + A_OFF(at & 1, 1));
        for (int q = 0; q < 4; ++q) {
            const uint32_t dcol = tmem + q * 128;
            const uint32_t qo = (uint32_t)(q * 1024);
            #pragma unroll
            for (int k = 0; k < 4; ++k)
                mma_f16_ss(dcol, adh + k * 2, bdh + qo + k * 2, IDESC, k != 0);
            #pragma unroll
            for (int k = 0; k < 4; ++k)
                mma_f16_ss(dcol, adh + k * 2, bdl + qo + k * 2, IDESC, 1);
            #pragma unroll
            for (int k = 0; k < 4; ++k)
                mma_f16_ss(dcol, adl + k * 2, bdh + qo + k * 2, IDESC, 1);
            mma_commit(sb + MB_QD(q));
        }
    };

    // prologue: MMA(0); build A(1)
    if (wid == 0 && nt > 0) { if (elect1()) issue_mma(0); }
    if (tid < 128 && nt > 1) build_A(1);

    const int sub = wid & 3;
    const int qh = wid >> 2;              // code quarter: cols [qh*128, qh*128+128)
    const int srow = sub * 32 + lane;
    const int cbase = qh * 128;
    const int rrow = tid & 127;           // refine row
    const int rq = tid >> 7;              // refine quarter

    // ---------- main loop ----------
    for (int it = 0; it < nt; ++it) {
        const int buf = it & 1;
        const int tile = bid + it * NCTA;

        // 1) wait this quarter's MMAs (issued a full tile of work ago -> fast path)
        mbar_wait(sb + MB_QD(qh), (uint32_t)(it & 1));
        fence_tc_after();

        // 2) branchless top-3 packed-key filter, software-pipelined LDTM
        uint32_t m1 = 0xFFFFFFFFu, m2 = 0xFFFFFFFFu, m3 = 0xFFFFFFFFu;
        {
            uint32_t rgA[32], rgB[32];
            LDTM_X32(rgA, tmem + cbase);
            tmem_wait_ld();
            #pragma unroll
            for (int b = 0; b < 4; ++b) {
                const uint32_t* cur = (b & 1) ? rgB : rgA;
                uint32_t* nxt = (b & 1) ? rgA : rgB;
                if (b < 3) LDTM_X32(nxt, tmem + cbase + (b + 1) * 32);
                const int base = cbase + b * 32;
                #pragma unroll
                for (int j4 = 0; j4 < 8; ++j4) {
                    float4 p4 = *(const float4*)(pre + base + j4 * 4);
                    #pragma unroll
                    for (int jj = 0; jj < 4; ++jj) {
                        float pv = (jj == 0) ? p4.x : (jj == 1) ? p4.y : (jj == 2) ? p4.z : p4.w;
                        float kf = __fmaf_rn(__uint_as_float(cur[j4 * 4 + jj]), NEG2SCALE, pv);
                        uint32_t pk = __float2uint_rz(kf) * 512u + (uint32_t)(base + j4 * 4 + jj);
                        uint32_t t1 = umx(m1, pk); m1 = umn(m1, pk);
                        uint32_t t2 = umx(m2, t1); m2 = umn(m2, t1);
                        m3 = umn(m3, t2);
                    }
                }
                if (b < 3) tmem_wait_ld();
            }
        }
        fence_tc_before();
        {
            uint4 u; u.x = m1; u.y = m2; u.z = m3; u.w = 0xFFFFFFFFu;
            *(uint4*)(QT + ((qh * 128 + srow) << 2)) = u;
        }
        __syncthreads();   // all TMEM reads done CTA-wide; QT visible

        // 3) issue MMA(it+1) NOW — overlaps refine + merge + gather + A build
        if (wid == 0 && it + 1 < nt) { if (elect1()) issue_mma(it + 1); }

        // 4) refine distributed over 512 threads: (row, quarter) each, top-3
        {
            const int grow = tile * ROWSB + rrow;
            float best = 3.4e38f; int bib = 0x7FFFFFFF;
            if (grow < n) {
                uint4 u0 = *(const uint4*)(QT + ((0 * 128 + rrow) << 2));
                uint4 u1 = *(const uint4*)(QT + ((1 * 128 + rrow) << 2));
                uint4 u2 = *(const uint4*)(QT + ((2 * 128 + rrow) << 2));
                uint4 u3 = *(const uint4*)(QT + ((3 * 128 + rrow) << 2));
                uint32_t gmin = umn(umn(u0.x, u1.x), umn(u2.x, u3.x));
                const uint32_t lim = gmin + MARG_P;
                uint4 mine = (rq == 0) ? u0 : (rq == 1) ? u1 : (rq == 2) ? u2 : u3;
                if (mine.x <= lim) {
                    const float xs = XsS[buf * 128 + rrow];
                    const float4* xr = (const float4*)(x + (size_t)grow * DD);
                    if (mine.z <= lim) {
                        // rare (R13-proven rate): 4th could hide behind top-3 -> quarter rescan
                        const int cb = rq * 128;
                        for (int code = cb; code < cb + 128; ++code) {
                            const float4* cr = (const float4*)(cbk + code * DD);
                            float dot = 0.0f;
                            #pragma unroll
                            for (int k4 = 0; k4 < 16; ++k4) {
                                float4 a = __ldg(xr + k4);
                                float4 bb = __ldg(cr + k4);
                                dot = __fmaf_rn(a.x, bb.x, dot);
                                dot = __fmaf_rn(a.y, bb.y, dot);
                                dot = __fmaf_rn(a.z, bb.z, dot);
                                dot = __fmaf_rn(a.w, bb.w, dot);
                            }
                            float d = __fmaf_rn(-2.0f, dot, __fadd_rn(xs, Cs[code]));
                            if (d < best) { best = d; bib = code; }  // ascending: lowest-index ties
                        }
                    } else {
                        uint32_t cand[2] = { mine.x, mine.y };
                        #pragma unroll
                        for (int i = 0; i < 2; ++i) {
                            if (cand[i] <= lim) {
                                const int code = (int)(cand[i] & 511u);
                                const float4* cr = (const float4*)(cbk + code * DD);
                                float dot = 0.0f;
                                #pragma unroll
                                for (int k4 = 0; k4 < 16; ++k4) {
                                    float4 a = __ldg(xr + k4);
                                    float4 bb = __ldg(cr + k4);
                                    dot = __fmaf_rn(a.x, bb.x, dot);
                                    dot = __fmaf_rn(a.y, bb.y, dot);
                                    dot = __fmaf_rn(a.z, bb.z, dot);
                                    dot = __fmaf_rn(a.w, bb.w, dot);
                                }
                                float t = __fadd_rn(xs, Cs[code]);
                                float d = __fmaf_rn(-2.0f, dot, t);
                                if (d < best || (d == best && code < bib)) { best = d; bib = code; }
                            }
                        }
                    }
                }
            }
            BD[rq * 128 + rrow] = best;
            BI[rq * 128 + rrow] = bib;
        }
        __syncthreads();

        // 5) merge 4 quarters (exact dist; equal -> lower code) -> index output
        if (tid < 128) {
            float bd = BD[tid]; int bi = BI[tid];
            #pragma unroll
            for (int g = 1; g < 4; ++g) {
                float d = BD[g * 128 + tid]; int ii = BI[g * 128 + tid];
                if (d < bd || (d == bd && ii < bi)) { bd = d; bi = ii; }
            }
            sidx[tid] = bi;
            const int g = tile * ROWSB + tid;
            if (g < n) out[2 * nD + g] = (float)bi;
        }
        __syncthreads();

        // 6) gather z_q_x / z_q_x_bar (overlaps MMA(it+1))
        for (int i = tid; i < ROWSB * 32; i += NTHR) {
            const int row = i >> 5;
            const int d = (i >> 4) & 1;
            const int q = i & 15;
            const int g = tile * ROWSB + row;
            if (g < n) {
                float4 v = __ldg(((const float4*)cbk) + sidx[row] * 16 + q);
                ((float4*)(out + (size_t)d * nD + (size_t)g * DD))[q] = v;
            }
        }

        // 7) build A(it+2) into buffer buf (A(it) dead; next iter's post-filter
        //    sync orders this build before MMA(it+2) issue; XsS[buf] overwrite is
        //    safe: refine of tile it finished before step-5 sync)
        if (tid < 128 && it + 2 < nt) build_A(it + 2);
    }

    __syncthreads();
    if (wid == 0) tmem_dealloc(tmem, 512);

#else
    // ============ generic-arch fallback (compile-only on GB300) ============
    for (int c = tid; c < KC; c += NTHR) {
        float s = 0.0f;
        const float* cr = cbk + c * DD;
        for (int k = 0; k < DD; ++k) {
            float v = cr[k];
            s = __fadd_rn(s, __fmul_rn(v, v));
        }
        Cs[c] = s;
    }
    __syncthreads();
    for (long long row = (long long)bid * NTHR + tid; row < n; row += (long long)gridDim.x * NTHR) {
        const float* xr = x + row * DD;
        float xv[DD];
        for (int k = 0; k < DD; ++k) xv[k] = xr[k];
        float xs = 0.0f;
        for (int k = 0; k < DD; ++k) xs = __fadd_rn(xs, __fmul_rn(xv[k], xv[k]));
        float best = 3.4e38f; int bi = 0;
        for (int c = 0; c < KC; ++c) {
            const float* cr = cbk + c * DD;
            float dot = 0.0f;
            for (int k = 0; k < DD; ++k) dot = __fmaf_rn(xv[k], cr[k], dot);
            float d = __fmaf_rn(-2.0f, dot, __fadd_rn(xs, Cs[c]));
            if (d < best) { best = d; bi = c; }
        }
        out[2 * nD + row] = (float)bi;
        const float* cr = cbk + bi * DD;
        for (int k = 0; k < DD; ++k) {
            out[(size_t)row * DD + k] = cr[k];
            out[nD + (size_t)row * DD + k] = cr[k];
        }
    }
#endif
}

extern "C" void kernel_launch(void* const* d_in, const int* in_sizes, int n_in,
                              void* d_out, int out_size) {
    const float* x = (const float*)d_in[0];
    const float* cbk = (const float*)d_in[1];
    float* out = (float*)d_out;
    const int n = in_sizes[0] / DD;

    cudaFuncSetAttribute(vq_persist, cudaFuncAttributeMaxDynamicSharedMemorySize, SMEM_TOTAL);
    vq_persist<<<NCTA, NTHR, SMEM_TOTAL>>>(x, cbk, out, n);
}